// round 1
// baseline (speedup 1.0000x reference)
#include <cuda_runtime.h>
#include <cstdint>

// Problem constants (fixed shapes per reference)
#define NSPANS 4096
#define TMAX   16
#define HDIM   768
#define H4     192          // HDIM / 4 (float4 lanes per row)
#define REPR4  576          // 3 * H4 float4 per span repr
#define NPAIRS 16384
#define SL     2048         // S * L

// Scratch: span representations [NSPANS, 3*HDIM] = 37.75 MB
__device__ float4 g_reprs[NSPANS * REPR4];

// Kernel 1: one block per span, 192 threads = one float4 lane each.
// Computes first / mean / last over the valid tokens only.
__global__ __launch_bounds__(H4) void reprs_kernel(
    const float* __restrict__ hidden,
    const int*   __restrict__ span_doc,
    const int*   __restrict__ span_tok,
    const int*   __restrict__ span_len)
{
    const int n    = blockIdx.x;
    const int lane = threadIdx.x;            // 0..191

    const int doc = __ldg(span_doc + n);
    const int len = __ldg(span_len + n);     // 1..16

    const float4* __restrict__ base =
        reinterpret_cast<const float4*>(hidden) + (size_t)doc * SL * H4;
    const int* __restrict__ toks = span_tok + n * TMAX;

    float4 first = make_float4(0.f, 0.f, 0.f, 0.f);
    float4 last  = first;
    float4 acc   = first;

    for (int t = 0; t < len; ++t) {
        const int tok = __ldg(toks + t);
        const float4 v = __ldg(base + (size_t)tok * H4 + lane);
        acc.x += v.x; acc.y += v.y; acc.z += v.z; acc.w += v.w;
        if (t == 0) first = v;
        last = v;                             // ends as g[len-1]
    }

    const float inv = 1.0f / (float)len;
    const float4 mean = make_float4(acc.x * inv, acc.y * inv,
                                    acc.z * inv, acc.w * inv);

    float4* __restrict__ out = g_reprs + (size_t)n * REPR4;
    out[lane]          = first;
    out[H4 + lane]     = mean;
    out[2 * H4 + lane] = last;
}

// Kernel 2: one block per pair, 384 threads x 3 iterations = 1152 float4
// (= 4608 floats) per output row. Fully coalesced stores; reads of g_reprs
// mostly hit L2 (37.7 MB working set).
__global__ __launch_bounds__(384) void pairs_kernel(
    const int* __restrict__ pair_i,
    const int* __restrict__ pair_j,
    float4*    __restrict__ out)
{
    const int p  = blockIdx.x;
    const int pi = __ldg(pair_i + p);
    const int pj = __ldg(pair_j + p);

    const float4* __restrict__ ri = g_reprs + (size_t)pi * REPR4;
    const float4* __restrict__ rj = g_reprs + (size_t)pj * REPR4;
    float4* __restrict__ o = out + (size_t)p * (2 * REPR4);

    #pragma unroll
    for (int k = 0; k < 3; ++k) {
        const int r = k * 384 + threadIdx.x;  // 0..1151
        float4 v;
        if (r < REPR4) v = __ldg(ri + r);
        else           v = __ldg(rj + (r - REPR4));
        o[r] = v;
    }
}

extern "C" void kernel_launch(void* const* d_in, const int* in_sizes, int n_in,
                              void* d_out, int out_size)
{
    const float* hidden   = (const float*)d_in[0];
    const int*   span_doc = (const int*)  d_in[1];
    const int*   span_tok = (const int*)  d_in[2];
    const int*   span_len = (const int*)  d_in[3];
    const int*   pair_i   = (const int*)  d_in[4];
    const int*   pair_j   = (const int*)  d_in[5];
    float4*      out      = (float4*)     d_out;

    reprs_kernel<<<NSPANS, H4>>>(hidden, span_doc, span_tok, span_len);
    pairs_kernel<<<NPAIRS, 384>>>(pair_i, pair_j, out);
}

// round 2
// speedup vs baseline: 1.1194x; 1.1194x over previous
#include <cuda_runtime.h>
#include <cstdint>

// Problem constants (fixed shapes per reference)
#define NSPANS 4096
#define TMAX   16
#define HDIM   768
#define H4     192          // HDIM / 4 (float4 lanes per row)
#define REPR4  576          // 3 * H4 float4 per span repr
#define NPAIRS 16384
#define SL     2048         // S * L

// Scratch: span representations [NSPANS, 3*HDIM] = 37.75 MB
__device__ float4 g_reprs[NSPANS * REPR4];

// Kernel 1: one block per span, 192 threads = one float4 lane each.
// Computes first / mean / last over the valid tokens only.
// Stores use default caching so the reprs land in L2 for kernel 2.
__global__ __launch_bounds__(H4) void reprs_kernel(
    const float* __restrict__ hidden,
    const int*   __restrict__ span_doc,
    const int*   __restrict__ span_tok,
    const int*   __restrict__ span_len)
{
    const int n    = blockIdx.x;
    const int lane = threadIdx.x;            // 0..191

    const int doc = __ldg(span_doc + n);
    const int len = __ldg(span_len + n);     // 1..16

    const float4* __restrict__ base =
        reinterpret_cast<const float4*>(hidden) + (size_t)doc * SL * H4;
    const int* __restrict__ toks = span_tok + n * TMAX;

    float4 first = make_float4(0.f, 0.f, 0.f, 0.f);
    float4 last  = first;
    float4 acc   = first;

    for (int t = 0; t < len; ++t) {
        const int tok = __ldg(toks + t);
        const float4 v = __ldg(base + (size_t)tok * H4 + lane);
        acc.x += v.x; acc.y += v.y; acc.z += v.z; acc.w += v.w;
        if (t == 0) first = v;
        last = v;                             // ends as g[len-1]
    }

    const float inv = 1.0f / (float)len;
    const float4 mean = make_float4(acc.x * inv, acc.y * inv,
                                    acc.z * inv, acc.w * inv);

    float4* __restrict__ out = g_reprs + (size_t)n * REPR4;
    out[lane]          = first;
    out[H4 + lane]     = mean;
    out[2 * H4 + lane] = last;
}

// Kernel 2: one block per pair, 384 threads. Each thread handles float4
// lanes {tid, tid+384, tid+768} of the 1152-float4 output row.
//   r0 = tid        in [0,384)   -> always from repr[i]
//   r1 = tid + 384  in [384,768) -> repr[i] if tid<192 else repr[j]
//   r2 = tid + 768  in [768,1152)-> always from repr[j]
// All three loads are issued before any store (MLP=3), and the 302 MB
// output stream uses streaming (evict-first) stores so g_reprs stays
// resident in L2.
__global__ __launch_bounds__(384) void pairs_kernel(
    const int* __restrict__ pair_i,
    const int* __restrict__ pair_j,
    float4*    __restrict__ out)
{
    const int p   = blockIdx.x;
    const int tid = threadIdx.x;
    const int pi  = __ldg(pair_i + p);
    const int pj  = __ldg(pair_j + p);

    const float4* __restrict__ ri = g_reprs + (size_t)pi * REPR4;
    const float4* __restrict__ rj = g_reprs + (size_t)pj * REPR4;
    float4* __restrict__ o = out + (size_t)p * (2 * REPR4);

    const float4 v0 = __ldg(ri + tid);
    const float4 v1 = (tid < 192) ? __ldg(ri + (tid + 384))
                                  : __ldg(rj + (tid - 192));
    const float4 v2 = __ldg(rj + (tid + 192));

    __stcs(o + tid,       v0);
    __stcs(o + tid + 384, v1);
    __stcs(o + tid + 768, v2);
}

extern "C" void kernel_launch(void* const* d_in, const int* in_sizes, int n_in,
                              void* d_out, int out_size)
{
    const float* hidden   = (const float*)d_in[0];
    const int*   span_doc = (const int*)  d_in[1];
    const int*   span_tok = (const int*)  d_in[2];
    const int*   span_len = (const int*)  d_in[3];
    const int*   pair_i   = (const int*)  d_in[4];
    const int*   pair_j   = (const int*)  d_in[5];
    float4*      out      = (float4*)     d_out;

    reprs_kernel<<<NSPANS, H4>>>(hidden, span_doc, span_tok, span_len);
    pairs_kernel<<<NPAIRS, 384>>>(pair_i, pair_j, out);
}